// round 8
// baseline (speedup 1.0000x reference)
#include <cuda_runtime.h>
#include <cuda_bf16.h>
#include <math.h>
#include <stdint.h>

// Problem constants
#define BATCH 2
#define SEQ   2048
#define CDIM  1024
#define NHEAD 16
#define HDIM  64
#define C3    (3*CDIM)          // 3072
#define MROWS (BATCH*SEQ)       // 4096

// Scratch (no cudaMalloc allowed)
__device__ float g_qkv[(size_t)MROWS * C3];       // [B,T,3,H,D] (tf32-rounded)
__device__ float g_attn[(size_t)MROWS * CDIM];    // [B,T,C]     (tf32-rounded)
__device__ float g_xr[(size_t)MROWS * CDIM];      // x, tf32-rounded
__device__ float g_wqkvt[(size_t)C3 * CDIM];      // Wqkv^T [3072][1024], tf32
__device__ float g_woutt[(size_t)CDIM * CDIM];    // Wout^T [1024][1024], tf32

__device__ __forceinline__ uint32_t f2tf32(float f) {
    uint32_t r;
    asm("cvt.rna.tf32.f32 %0, %1;" : "=r"(r) : "f"(f));
    return r;
}
__device__ __forceinline__ float fexp2(float x) {
    float y;
    asm("ex2.approx.f32 %0, %1;" : "=f"(y) : "f"(x));
    return y;
}
__device__ __forceinline__ uint32_t smem_u32(const void* p) {
    uint32_t a;
    asm("{ .reg .u64 t; cvta.to.shared.u64 t, %1; cvt.u32.u64 %0, t; }" : "=r"(a) : "l"(p));
    return a;
}
#define CP_ASYNC16(dst_u32, src_ptr) \
    asm volatile("cp.async.cg.shared.global [%0], [%1], 16;" :: "r"(dst_u32), "l"(src_ptr) : "memory")
#define CP_COMMIT() asm volatile("cp.async.commit_group;" ::: "memory")
#define CP_WAIT0()  asm volatile("cp.async.wait_group 0;" ::: "memory")
#define CP_WAIT1()  asm volatile("cp.async.wait_group 1;" ::: "memory")
#define CP_WAIT2()  asm volatile("cp.async.wait_group 2;" ::: "memory")

__device__ __forceinline__ void mma_tf32(float c[4], const uint32_t a[4], const uint32_t b[2]) {
    asm volatile(
        "mma.sync.aligned.m16n8k8.row.col.f32.tf32.tf32.f32 "
        "{%0,%1,%2,%3}, {%4,%5,%6,%7}, {%8,%9}, {%0,%1,%2,%3};"
        : "+f"(c[0]), "+f"(c[1]), "+f"(c[2]), "+f"(c[3])
        : "r"(a[0]), "r"(a[1]), "r"(a[2]), "r"(a[3]), "r"(b[0]), "r"(b[1]));
}
__device__ __forceinline__ void ldsm_x4(uint32_t r[4], uint32_t addr) {
    asm volatile("ldmatrix.sync.aligned.m8n8.x4.shared.b16 {%0,%1,%2,%3}, [%4];"
                 : "=r"(r[0]), "=r"(r[1]), "=r"(r[2]), "=r"(r[3]) : "r"(addr));
}

// ---------------------------------------------------------------------------
// Pre-pass 1: round x to tf32 (copy)
// ---------------------------------------------------------------------------
__global__ __launch_bounds__(256)
void round_kernel(const float* __restrict__ in, float* __restrict__ out, int n4)
{
    int i = blockIdx.x * blockDim.x + threadIdx.x;
    if (i < n4) {
        float4 v = ((const float4*)in)[i];
        float4 o;
        o.x = __uint_as_float(f2tf32(v.x));
        o.y = __uint_as_float(f2tf32(v.y));
        o.z = __uint_as_float(f2tf32(v.z));
        o.w = __uint_as_float(f2tf32(v.w));
        ((float4*)out)[i] = o;
    }
}

// ---------------------------------------------------------------------------
// Pre-pass 2: out[n][k] = tf32(in[k][n])  (weight transpose + round)
// ---------------------------------------------------------------------------
__global__ __launch_bounds__(256)
void transpose_round_kernel(const float* __restrict__ in, float* __restrict__ out,
                            int K, int N)
{
    __shared__ float tile[32][33];
    const int k0 = blockIdx.y * 32;
    const int n0 = blockIdx.x * 32;
    const int tx = threadIdx.x & 31;
    const int ty = threadIdx.x >> 5;     // 0..7
    #pragma unroll
    for (int i = 0; i < 32; i += 8)
        tile[ty + i][tx] = in[(size_t)(k0 + ty + i) * N + n0 + tx];
    __syncthreads();
    #pragma unroll
    for (int i = 0; i < 32; i += 8)
        out[(size_t)(n0 + ty + i) * K + k0 + tx] =
            __uint_as_float(f2tf32(tile[tx][ty + i]));
}

// ---------------------------------------------------------------------------
// tf32 mma.sync GEMM + bias: C[M,N] = A[M,K] @ Bt[N,K]^T + bias[N]
// A [M][K], Bt [N][K] (both tf32-pre-rounded). cp.async 3-stage; fragment
// loads via ldmatrix.x4 (A and B both [row][k] 32-float tiles, stride 36).
// CTA 128x128, BK=32, 8 warps (2x4), warp tile 64x32.
// ---------------------------------------------------------------------------
#define GBM 128
#define GBN 128
#define GBK 32
#define T_STRIDE 36
#define TILE_FLOATS (128 * T_STRIDE)        // 4608 (each of A, Bt)
#define STG_FLOATS (2 * TILE_FLOATS)        // 9216
#define GEMM_SMEM (3 * STG_FLOATS * 4)      // 110592 B

template<bool RND>
__global__ __launch_bounds__(256)
void gemm_tc_kernel(const float* __restrict__ A,
                    const float* __restrict__ Bt,
                    const float* __restrict__ bias,
                    float* __restrict__ C,
                    int M, int N, int K)
{
    extern __shared__ float smem[];
    const int tid = threadIdx.x;
    const int wid = tid >> 5;
    const int l   = tid & 31;
    const int warpM = wid >> 2;
    const int warpN = wid & 3;
    const int rowbase = blockIdx.y * GBM;
    const int colbase = blockIdx.x * GBN;

    const uint32_t smb = smem_u32(smem);

    // ldmatrix per-lane addressing: quad = l/8
    const int quad = l >> 3;
    const int lrow = ((quad & 1) << 3) + (l & 7);   // row within 16-row block
    const int lcol = (quad >> 1) << 2;              // 0 or 4 (float col offset)

    float acc[4][4][4];
    #pragma unroll
    for (int i = 0; i < 4; i++)
        #pragma unroll
        for (int j = 0; j < 4; j++)
            #pragma unroll
            for (int q = 0; q < 4; q++) acc[i][j][q] = 0.f;

    const int g_r = tid >> 3, g_c = (tid & 7) * 4;  // loader mapping (both tiles)

    const int S = K / GBK;

    auto load_stage = [&](int stg, int k0) {
        const uint32_t sa = smb + stg * STG_FLOATS * 4;
        const uint32_t sb = sa + TILE_FLOATS * 4;
        #pragma unroll
        for (int it = 0; it < 4; it++) {
            const int r = it * 32 + g_r;
            CP_ASYNC16(sa + (uint32_t)(r * T_STRIDE + g_c) * 4,
                       A + (size_t)(rowbase + r) * K + k0 + g_c);
            CP_ASYNC16(sb + (uint32_t)(r * T_STRIDE + g_c) * 4,
                       Bt + (size_t)(colbase + r) * K + k0 + g_c);
        }
        CP_COMMIT();
    };

    load_stage(0, 0);
    load_stage(1, GBK);

    for (int s = 0; s < S; s++) {
        if (s + 2 < S) { load_stage((s + 2) % 3, (s + 2) * GBK); CP_WAIT2(); }
        else if (s + 1 < S) { CP_WAIT1(); }
        else { CP_WAIT0(); }
        __syncthreads();

        const uint32_t sa = smb + (s % 3) * STG_FLOATS * 4;
        const uint32_t sb = sa + TILE_FLOATS * 4;
        #pragma unroll
        for (int ks = 0; ks < 4; ks++) {
            const int kk4 = ks * 8 + lcol;
            uint32_t af[4][4], bfm[2][4];
            #pragma unroll
            for (int i = 0; i < 4; i++)
                ldsm_x4(af[i], sa + (uint32_t)((warpM * 64 + i * 16 + lrow) * T_STRIDE + kk4) * 4);
            #pragma unroll
            for (int j2 = 0; j2 < 2; j2++)
                ldsm_x4(bfm[j2], sb + (uint32_t)((warpN * 32 + j2 * 16 + lrow) * T_STRIDE + kk4) * 4);
            #pragma unroll
            for (int i = 0; i < 4; i++)
                #pragma unroll
                for (int j = 0; j < 4; j++) {
                    uint32_t bf[2] = { bfm[j >> 1][j & 1], bfm[j >> 1][(j & 1) + 2] };
                    mma_tf32(acc[i][j], af[i], bf);
                }
        }
        __syncthreads();
    }

    const int erow = rowbase + warpM * 64 + (l >> 2);
    const int ecol = colbase + warpN * 32 + 2 * (l & 3);
    #pragma unroll
    for (int i = 0; i < 4; i++) {
        #pragma unroll
        for (int j = 0; j < 4; j++) {
            const int r0 = erow + i * 16;
            const int c0 = ecol + j * 8;
            const float b0 = bias[c0], b1 = bias[c0 + 1];
            float2 v0, v1;
            if (RND) {
                v0.x = __uint_as_float(f2tf32(acc[i][j][0] + b0));
                v0.y = __uint_as_float(f2tf32(acc[i][j][1] + b1));
                v1.x = __uint_as_float(f2tf32(acc[i][j][2] + b0));
                v1.y = __uint_as_float(f2tf32(acc[i][j][3] + b1));
            } else {
                v0.x = acc[i][j][0] + b0; v0.y = acc[i][j][1] + b1;
                v1.x = acc[i][j][2] + b0; v1.y = acc[i][j][3] + b1;
            }
            *(float2*)(C + (size_t)r0 * N + c0)       = v0;
            *(float2*)(C + (size_t)(r0 + 8) * N + c0) = v1;
        }
    }
}

// ---------------------------------------------------------------------------
// Tensor-core flash attention: cp.async double-buffered K/V, ldmatrix for
// K (S-mma B frags) and P (PV A frags), scale folded into Q, mask skip.
// CTA = 128 q rows of one (b,h); 8 warps x 16 rows. K-tile = 64 keys.
// ---------------------------------------------------------------------------
#define AQ 128
#define AK 64
#define KS_STRIDE 68
#define VS_STRIDE 72
#define PS_STRIDE 68
#define KS_FLOATS (AK * KS_STRIDE)
#define VS_FLOATS (AK * VS_STRIDE)
#define KV_FLOATS (KS_FLOATS + VS_FLOATS)
#define PS_FLOATS (8 * 16 * PS_STRIDE)
#define ATTN_SMEM ((2 * KV_FLOATS + PS_FLOATS) * 4)   // 106496 B

__global__ __launch_bounds__(256)
void attn_tc_kernel(const float* __restrict__ qkv, float* __restrict__ out)
{
    extern __shared__ float sm[];
    float* Psm = sm + 2 * KV_FLOATS;

    const int qtile = blockIdx.x;
    const int h   = blockIdx.y;
    const int b   = blockIdx.z;
    const int tid = threadIdx.x;
    const int wid = tid >> 5;
    const int l   = tid & 31;
    const int g   = l >> 2;
    const int t   = l & 3;
    const int qb  = qtile * AQ;
    const int rg  = qb + wid * 16 + g;

    const int quad = l >> 3;
    const int lrow = ((quad & 1) << 3) + (l & 7);
    const int lcol = (quad >> 1) << 2;

    const float SC = 0.18033688011112042f;   // (1/sqrt(64)) * log2(e)
    float* Pw = Psm + wid * (16 * PS_STRIDE);
    const uint32_t smb = smem_u32(sm);
    const uint32_t pwb = smb + (uint32_t)(2 * KV_FLOATS + wid * 16 * PS_STRIDE) * 4;

    auto load_kv = [&](int stg, int kb) {
        const uint32_t kbuf = smb + stg * KV_FLOATS * 4;
        const uint32_t vbuf = kbuf + KS_FLOATS * 4;
        #pragma unroll
        for (int it = 0; it < 4; it++) {
            const int idx = it * 256 + tid;
            const int r = idx >> 4;
            const int c = (idx & 15) * 4;
            const float* src = qkv + (size_t)(b * SEQ + kb + r) * C3 + h * HDIM + c;
            CP_ASYNC16(kbuf + (uint32_t)(r * KS_STRIDE + c) * 4, src + CDIM);
            CP_ASYNC16(vbuf + (uint32_t)(r * VS_STRIDE + c) * 4, src + 2 * CDIM);
        }
        CP_COMMIT();
    };

    // Q fragments with softmax scale pre-folded (tf32-rounded)
    uint32_t qa[8][4];
    {
        const float* Qr  = qkv + (size_t)(b * SEQ + rg    ) * C3 + h * HDIM;
        const float* Qr8 = qkv + (size_t)(b * SEQ + rg + 8) * C3 + h * HDIM;
        #pragma unroll
        for (int ks = 0; ks < 8; ks++) {
            qa[ks][0] = f2tf32(Qr [ks * 8 + t]     * SC);
            qa[ks][1] = f2tf32(Qr8[ks * 8 + t]     * SC);
            qa[ks][2] = f2tf32(Qr [ks * 8 + t + 4] * SC);
            qa[ks][3] = f2tf32(Qr8[ks * 8 + t + 4] * SC);
        }
    }

    float O[8][4];
    #pragma unroll
    for (int nb = 0; nb < 8; nb++)
        #pragma unroll
        for (int q = 0; q < 4; q++) O[nb][q] = 0.f;
    float m0 = -INFINITY, m1 = -INFINITY, l0 = 0.f, l1 = 0.f;

    const int ntiles = (qb + AQ) / AK;

    load_kv(0, 0);

    for (int ti = 0; ti < ntiles; ti++) {
        if (ti + 1 < ntiles) { load_kv((ti + 1) & 1, (ti + 1) * AK); CP_WAIT1(); }
        else { CP_WAIT0(); }
        __syncthreads();

        const uint32_t kbase = smb + (uint32_t)((ti & 1) * KV_FLOATS) * 4;
        const float* Vsm = sm + (ti & 1) * KV_FLOATS + KS_FLOATS;
        const int kb = ti * AK;

        // S = Q @ K^T  (K fragments via ldmatrix; Ksm is [key][d] = [n][k])
        float sc[8][4];
        #pragma unroll
        for (int nb = 0; nb < 8; nb++) {
            sc[nb][0] = 0.f; sc[nb][1] = 0.f; sc[nb][2] = 0.f; sc[nb][3] = 0.f;
        }
        #pragma unroll
        for (int ks = 0; ks < 8; ks++) {
            uint32_t bfm[4][4];
            #pragma unroll
            for (int j2 = 0; j2 < 4; j2++)
                ldsm_x4(bfm[j2], kbase + (uint32_t)((j2 * 16 + lrow) * KS_STRIDE + ks * 8 + lcol) * 4);
            #pragma unroll
            for (int j2 = 0; j2 < 4; j2++) {
                uint32_t bf0[2] = { bfm[j2][0], bfm[j2][2] };
                uint32_t bf1[2] = { bfm[j2][1], bfm[j2][3] };
                mma_tf32(sc[2 * j2    ], qa[ks], bf0);
                mma_tf32(sc[2 * j2 + 1], qa[ks], bf1);
            }
        }

        // Causal mask only on diagonal-overlapping tiles
        const bool needmask = (kb + AK - 1) > (qb + wid * 16);
        float tm0 = -INFINITY, tm1 = -INFINITY;
        if (needmask) {
            #pragma unroll
            for (int nb = 0; nb < 8; nb++) {
                const int k0 = kb + nb * 8 + 2 * t;
                if (k0     > rg    ) sc[nb][0] = -INFINITY;
                if (k0 + 1 > rg    ) sc[nb][1] = -INFINITY;
                if (k0     > rg + 8) sc[nb][2] = -INFINITY;
                if (k0 + 1 > rg + 8) sc[nb][3] = -INFINITY;
                tm0 = fmaxf(tm0, fmaxf(sc[nb][0], sc[nb][1]));
                tm1 = fmaxf(tm1, fmaxf(sc[nb][2], sc[nb][3]));
            }
        } else {
            #pragma unroll
            for (int nb = 0; nb < 8; nb++) {
                tm0 = fmaxf(tm0, fmaxf(sc[nb][0], sc[nb][1]));
                tm1 = fmaxf(tm1, fmaxf(sc[nb][2], sc[nb][3]));
            }
        }
        tm0 = fmaxf(tm0, __shfl_xor_sync(0xffffffffu, tm0, 1));
        tm0 = fmaxf(tm0, __shfl_xor_sync(0xffffffffu, tm0, 2));
        tm1 = fmaxf(tm1, __shfl_xor_sync(0xffffffffu, tm1, 1));
        tm1 = fmaxf(tm1, __shfl_xor_sync(0xffffffffu, tm1, 2));

        const float nm0 = fmaxf(m0, tm0);
        const float nm1 = fmaxf(m1, tm1);
        const float c0 = fexp2(m0 - nm0);
        const float c1 = fexp2(m1 - nm1);
        l0 *= c0; l1 *= c1;
        #pragma unroll
        for (int nb = 0; nb < 8; nb++) {
            O[nb][0] *= c0; O[nb][1] *= c0;
            O[nb][2] *= c1; O[nb][3] *= c1;
        }
        m0 = nm0; m1 = nm1;

        #pragma unroll
        for (int nb = 0; nb < 8; nb++) {
            float p0 = fexp2(sc[nb][0] - m0);
            float p1 = fexp2(sc[nb][1] - m0);
            float p2 = fexp2(sc[nb][2] - m1);
            float p3 = fexp2(sc[nb][3] - m1);
            l0 += p0 + p1;
            l1 += p2 + p3;
            uint2 u0 = { f2tf32(p0), f2tf32(p1) };
            uint2 u1 = { f2tf32(p2), f2tf32(p3) };
            *(uint2*)(Pw + (g    ) * PS_STRIDE + nb * 8 + 2 * t) = u0;
            *(uint2*)(Pw + (g + 8) * PS_STRIDE + nb * 8 + 2 * t) = u1;
        }
        __syncwarp();

        // O += P @ V  (P fragments via ldmatrix; V scalar B-frags)
        #pragma unroll
        for (int ks = 0; ks < 8; ks++) {
            uint32_t pa[4];
            ldsm_x4(pa, pwb + (uint32_t)(lrow * PS_STRIDE + ks * 8 + lcol) * 4);
            #pragma unroll
            for (int nb = 0; nb < 8; nb++) {
                uint32_t bf[2];
                bf[0] = __float_as_uint(Vsm[(ks * 8 + t    ) * VS_STRIDE + nb * 8 + g]);
                bf[1] = __float_as_uint(Vsm[(ks * 8 + t + 4) * VS_STRIDE + nb * 8 + g]);
                mma_tf32(O[nb], pa, bf);
            }
        }
        __syncthreads();   // all warps done with this K/V buffer before reload
    }

    l0 += __shfl_xor_sync(0xffffffffu, l0, 1);
    l0 += __shfl_xor_sync(0xffffffffu, l0, 2);
    l1 += __shfl_xor_sync(0xffffffffu, l1, 1);
    l1 += __shfl_xor_sync(0xffffffffu, l1, 2);
    const float inv0 = 1.f / l0;
    const float inv1 = 1.f / l1;

    float* out0 = out + (size_t)(b * SEQ + rg    ) * CDIM + h * HDIM;
    float* out8 = out + (size_t)(b * SEQ + rg + 8) * CDIM + h * HDIM;
    #pragma unroll
    for (int nb = 0; nb < 8; nb++) {
        float2 v0, v1;
        v0.x = __uint_as_float(f2tf32(O[nb][0] * inv0));
        v0.y = __uint_as_float(f2tf32(O[nb][1] * inv0));
        v1.x = __uint_as_float(f2tf32(O[nb][2] * inv1));
        v1.y = __uint_as_float(f2tf32(O[nb][3] * inv1));
        *(float2*)(out0 + nb * 8 + 2 * t) = v0;
        *(float2*)(out8 + nb * 8 + 2 * t) = v1;
    }
}

// ---------------------------------------------------------------------------
// Launch
// ---------------------------------------------------------------------------
extern "C" void kernel_launch(void* const* d_in, const int* in_sizes, int n_in,
                              void* d_out, int out_size)
{
    const float* x    = (const float*)d_in[0];
    const float* Wqkv = (const float*)d_in[1];
    const float* bqkv = (const float*)d_in[2];
    const float* Wout = (const float*)d_in[3];
    const float* bout = (const float*)d_in[4];
    float* out = (float*)d_out;

    float *qkv, *attn, *xr, *wqkvt, *woutt;
    cudaGetSymbolAddress((void**)&qkv,   g_qkv);
    cudaGetSymbolAddress((void**)&attn,  g_attn);
    cudaGetSymbolAddress((void**)&xr,    g_xr);
    cudaGetSymbolAddress((void**)&wqkvt, g_wqkvt);
    cudaGetSymbolAddress((void**)&woutt, g_woutt);

    static bool attr_set = false;
    if (!attr_set) {
        cudaFuncSetAttribute(gemm_tc_kernel<true>,  cudaFuncAttributeMaxDynamicSharedMemorySize, GEMM_SMEM);
        cudaFuncSetAttribute(gemm_tc_kernel<false>, cudaFuncAttributeMaxDynamicSharedMemorySize, GEMM_SMEM);
        cudaFuncSetAttribute(attn_tc_kernel, cudaFuncAttributeMaxDynamicSharedMemorySize, ATTN_SMEM);
        attr_set = true;
    }

    // 0) Pre-round x; transpose+round weights
    round_kernel<<<(MROWS * CDIM / 4 + 255) / 256, 256>>>(x, xr, MROWS * CDIM / 4);
    {
        dim3 grid(C3 / 32, CDIM / 32);
        transpose_round_kernel<<<grid, 256>>>(Wqkv, wqkvt, CDIM, C3);
    }
    {
        dim3 grid(CDIM / 32, CDIM / 32);
        transpose_round_kernel<<<grid, 256>>>(Wout, woutt, CDIM, CDIM);
    }

    // 1) QKV projection (rounds outputs -> attention operands pre-rounded)
    {
        dim3 grid(C3 / GBN, MROWS / GBM);
        gemm_tc_kernel<true><<<grid, 256, GEMM_SMEM>>>(xr, wqkvt, bqkv, qkv, MROWS, C3, CDIM);
    }
    // 2) Causal flash attention (tensor cores) -> g_attn (tf32-rounded)
    {
        dim3 grid(SEQ / AQ, NHEAD, BATCH);
        attn_tc_kernel<<<grid, 256, ATTN_SMEM>>>(qkv, attn);
    }
    // 3) Output projection (fp32 output)
    {
        dim3 grid(CDIM / GBN, MROWS / GBM);
        gemm_tc_kernel<false><<<grid, 256, GEMM_SMEM>>>(attn, woutt, bout, out, MROWS, CDIM, CDIM);
    }
}